// round 6
// baseline (speedup 1.0000x reference)
#include <cuda_runtime.h>
#include <cstdint>

// ---------------------------------------------------------------------------
// GCN_OUTPRODUCT: B=16, C=32, T=128, J=25, O=64
// ---------------------------------------------------------------------------

#define NB 16
#define NC 32
#define NT 128
#define NJ 25
#define NO 64
#define EPSBN 1e-5f

// xcl layout: per (b, channel) row = [28 zero pad][3200 interior][28 zero pad]
#define XLS 3256
#define XLP 28

// scratch (static device allocations; allowed)
__device__ __align__(16) float g_An[NJ * NJ];
__device__ __align__(16) float g_A2[NJ * NJ];
__device__ __align__(16) float g_WQ[32 * 544 * 2];      // [o][r]{hi,lo} qform W
__device__ __align__(16) float2 g_WA2[64 * 288];        // Wt {hi,lo}, [o][k]
__device__ __align__(16) float g_xc[NB * 96 * NT * NJ]; // concat branches (tf32 hi)
__device__ __align__(16) float g_xcl[NB * 96 * XLS];    // tf32 lo residual, padded
__device__ __align__(16) float g_y[NB * NO * NT * NJ];  // post-relu conv out
__device__ __align__(16) float g_part[128 * 256];       // [chan-stat][block]
__device__ __align__(16) float g_scsh[128];             // scale / shift

// ---------------------------------------------------------------------------
// mma.sync tf32 helpers
// ---------------------------------------------------------------------------
__device__ __forceinline__ uint32_t f2tf32(float x) {
    uint32_t r;
    asm("cvt.rna.tf32.f32 %0, %1;" : "=r"(r) : "f"(x));
    return r;
}

__device__ __forceinline__ void mma_tf32(float* d,
                                         uint32_t a0, uint32_t a1,
                                         uint32_t a2, uint32_t a3,
                                         uint32_t b0, uint32_t b1) {
    asm volatile(
        "mma.sync.aligned.m16n8k8.row.col.f32.tf32.tf32.f32 "
        "{%0,%1,%2,%3}, {%4,%5,%6,%7}, {%8,%9}, {%0,%1,%2,%3};"
        : "+f"(d[0]), "+f"(d[1]), "+f"(d[2]), "+f"(d[3])
        : "r"(a0), "r"(a1), "r"(a2), "r"(a3), "r"(b0), "r"(b1));
}

// split v into tf32 hi (as float) and tf32 lo residual (as float)
__device__ __forceinline__ void split_tf32(float v, float& hi, float& lo) {
    hi = __uint_as_float(f2tf32(v));
    lo = __uint_as_float(f2tf32(v - hi));
}

// ---------------------------------------------------------------------------
// K0: graph matrices + symmetrized-split W3 + tf32 hi/lo split of Wt + pads
// ---------------------------------------------------------------------------
__global__ void k0_prep(const float* __restrict__ A,
                        const float* __restrict__ W3,
                        const float* __restrict__ Wt) {
    int tid = threadIdx.x;
    if (blockIdx.x == 0) {
        __shared__ float d[NJ], dw[NJ];
        if (tid < NJ) {
            float s = 0.f;
            for (int k = 0; k < NJ; ++k) s += A[tid * NJ + k];
            d[tid] = s;
            dw[tid] = s - A[tid * NJ + tid];  // Aw = A - I row sum
        }
        __syncthreads();
        for (int idx = tid; idx < NJ * NJ; idx += blockDim.x) {
            int j = idx / NJ, k = idx % NJ;
            g_An[idx] = A[idx] * rsqrtf(d[j] * d[k]);
            g_A2[idx] = (j == k) ? dw[j] : -A[idx];
        }
    }
    int gtid = blockIdx.x * blockDim.x + tid;
    int stride = gridDim.x * blockDim.x;
    // g_WQ[o][r] = {hi,lo} of symmetric pair coeff; r=(c1*17+dd), c2=(c1+dd)&31
    for (int idx = gtid; idx < 32 * 544; idx += stride) {
        int o = idx / 544, r = idx % 544;
        int c1 = r / 17, dd = r % 17;
        int c2 = (c1 + dd) & 31;
        float v;
        if (dd == 0) {
            v = W3[o * 1024 + c1 * 32 + c1];
        } else {
            v = W3[o * 1024 + c1 * 32 + c2] + W3[o * 1024 + c2 * 32 + c1];
            if (dd == 16) v *= 0.5f;  // distance-16 pairs enumerated twice
        }
        float hi, lo;
        split_tf32(v, hi, lo);
        g_WQ[idx * 2] = hi;
        g_WQ[idx * 2 + 1] = lo;
    }
    // Wt hi/lo split, interleaved float2 (layout [o][i*3+dt])
    for (int idx = gtid; idx < 64 * 288; idx += stride) {
        float hi, lo;
        split_tf32(Wt[idx], hi, lo);
        g_WA2[idx] = make_float2(hi, lo);
    }
    // zero halo pads of g_xcl: 1536 rows x 56 pad floats
    for (int idx = gtid; idx < 1536 * 56; idx += stride) {
        int row = idx / 56, q = idx % 56;
        int col = (q < XLP) ? q : (XLS - 56 + q);
        g_xcl[row * XLS + col] = 0.f;
    }
}

// ---------------------------------------------------------------------------
// K1: per (b, 4-t chunk): graph convs + pw convs + qform via tensor cores
// grid = 16 * 32 = 512 blocks, 256 threads
// smem tiles use STRIDE=104 (100 positions + 4 zero pad -> 13 n8-tiles)
// All shared arrays 16B-aligned (float4 LDS/LDG.128 paths require it).
// ---------------------------------------------------------------------------
#define STR 104
__global__ void __launch_bounds__(256) k1_branches(
    const float* __restrict__ x,
    const float* __restrict__ W1, const float* __restrict__ b1,
    const float* __restrict__ W2, const float* __restrict__ b2,
    const float* __restrict__ b3) {
    __shared__ __align__(16) float sA[32 * STR];   // x slice, later G1
    __shared__ __align__(16) float sB[32 * STR];   // G2
    __shared__ __align__(16) float sW1[32 * 32];
    __shared__ __align__(16) float sW2[32 * 32];
    __shared__ __align__(16) uint32_t soff[544];   // (c1*STR)<<16 | (c2*STR)
    __shared__ __align__(16) float sAn[NJ * NJ];
    __shared__ __align__(16) float sA2[NJ * NJ];

    int tid = threadIdx.x;
    int b = blockIdx.x >> 5;
    int t0 = (blockIdx.x & 31) * 4;

    // load x slice [c][col], zero pad cols 100..103 (both tiles)
    for (int idx = tid; idx < 32 * STR; idx += 256) {
        int c = idx / STR, q = idx % STR;
        float v = 0.f;
        if (q < 100) {
            int tt = q / 25, j = q % 25;
            v = x[((b * 32 + c) * 128 + t0 + tt) * 25 + j];
        }
        sA[idx] = v;
        if (q >= 100) sB[idx] = 0.f;
    }
    for (int idx = tid; idx < NJ * NJ; idx += 256) {
        sAn[idx] = g_An[idx];
        sA2[idx] = g_A2[idx];
    }
    for (int idx = tid; idx < 1024; idx += 256) {
        sW1[idx] = W1[idx];
        sW2[idx] = W2[idx];
    }
    for (int idx = tid; idx < 544; idx += 256) {
        int c1 = idx / 17, dd = idx % 17;
        int c2 = (c1 + dd) & 31;
        soff[idx] = ((uint32_t)(c1 * STR) << 16) | (uint32_t)(c2 * STR);
    }
    __syncthreads();

    // graph convs -> registers (so G1 can overwrite x buffer)
    float r1[13], r2[13];
#pragma unroll
    for (int it = 0; it < 13; ++it) {
        int idx = tid + it * 256;
        float a1 = 0.f, a2 = 0.f;
        if (idx < 3200) {
            int c = idx / 100, q = idx % 100;
            int tt = q / 25, k = q % 25;
            const float* xr = &sA[c * STR + tt * 25];
#pragma unroll
            for (int j = 0; j < 25; ++j) {
                float xv = xr[j];
                a1 += xv * sAn[j * 25 + k];
                a2 += xv * sA2[j * 25 + k];
            }
        }
        r1[it] = a1;
        r2[it] = a2;
    }
    __syncthreads();
#pragma unroll
    for (int it = 0; it < 13; ++it) {
        int idx = tid + it * 256;
        if (idx < 3200) {
            int c = idx / 100, q = idx % 100;
            sA[c * STR + q] = r1[it];
            sB[c * STR + q] = r2[it];
        }
    }
    __syncthreads();

    // pointwise convs, vectorized: 1600 units = which(2) x o(32) x p4(25)
    // per unit: 4 consecutive positions, all 32 input channels
    for (int u = tid; u < 1600; u += 256) {
        int p4 = u % 25;
        int o = (u / 25) & 31;
        int which = (u >= 800) ? 1 : 0;
        const float* G = which ? sB : sA;
        const float4* W4 =
            reinterpret_cast<const float4*>(which ? sW2 : sW1) + o * 8;
        float bias = which ? __ldg(&b2[o]) : __ldg(&b1[o]);
        float4 acc = make_float4(bias, bias, bias, bias);
#pragma unroll
        for (int c4 = 0; c4 < 8; ++c4) {
            float4 w = W4[c4];
            const float* g0 = &G[(c4 * 4) * STR + p4 * 4];
            float4 ga = *reinterpret_cast<const float4*>(g0);
            float4 gb = *reinterpret_cast<const float4*>(g0 + STR);
            float4 gc = *reinterpret_cast<const float4*>(g0 + 2 * STR);
            float4 gd = *reinterpret_cast<const float4*>(g0 + 3 * STR);
            acc.x += w.x * ga.x + w.y * gb.x + w.z * gc.x + w.w * gd.x;
            acc.y += w.x * ga.y + w.y * gb.y + w.z * gc.y + w.w * gd.y;
            acc.z += w.x * ga.z + w.y * gb.z + w.z * gc.z + w.w * gd.z;
            acc.w += w.x * ga.w + w.y * gb.w + w.z * gc.w + w.w * gd.w;
        }
        acc.x = fmaxf(acc.x, 0.f);
        acc.y = fmaxf(acc.y, 0.f);
        acc.z = fmaxf(acc.z, 0.f);
        acc.w = fmaxf(acc.w, 0.f);
        float4 hi, lo;
        split_tf32(acc.x, hi.x, lo.x);
        split_tf32(acc.y, hi.y, lo.y);
        split_tf32(acc.z, hi.z, lo.z);
        split_tf32(acc.w, hi.w, lo.w);
        int ch = b * 96 + which * 32 + o;
        *reinterpret_cast<float4*>(&g_xc[ch * 3200 + t0 * 25 + p4 * 4]) = hi;
        *reinterpret_cast<float4*>(&g_xcl[ch * XLS + XLP + t0 * 25 + p4 * 4]) = lo;
    }

    // ---- quadratic form on tensor cores ----
    // C[32,100] = WQ^T[32,544] x Q[544,100], Q[r,p] = v_c1[p]*v_c2[p]
    int warp = tid >> 5, lane = tid & 31;
    int g = lane >> 2, c = lane & 3;
    int mt = warp & 1;
    int nq = warp >> 1;
    int nt0 = (nq == 0) ? 0 : (1 + 3 * nq);
    int ntN = (nq == 0) ? 4 : 3;
    int o0 = mt * 16;
    int olo = o0 + g, ohi = o0 + g + 8;

    float Cq[4][4];
#pragma unroll
    for (int n = 0; n < 4; ++n) {
        Cq[n][0] = 0.f; Cq[n][1] = 0.f; Cq[n][2] = 0.f; Cq[n][3] = 0.f;
    }

    const float2* WQ2 = reinterpret_cast<const float2*>(g_WQ);

#pragma unroll 2
    for (int kt = 0; kt < 68; ++kt) {
        int r0 = kt * 8 + c, r1i = r0 + 4;
        uint32_t pk0 = soff[r0], pk1 = soff[r1i];
        int a0o = pk0 >> 16, a0t = pk0 & 0xffff;
        int a1o = pk1 >> 16, a1t = pk1 & 0xffff;
        float2 w0 = __ldg(&WQ2[olo * 544 + r0]);
        float2 w1 = __ldg(&WQ2[ohi * 544 + r0]);
        float2 w2 = __ldg(&WQ2[olo * 544 + r1i]);
        float2 w3 = __ldg(&WQ2[ohi * 544 + r1i]);
        uint32_t Ah0 = __float_as_uint(w0.x), Al0 = __float_as_uint(w0.y);
        uint32_t Ah1 = __float_as_uint(w1.x), Al1 = __float_as_uint(w1.y);
        uint32_t Ah2 = __float_as_uint(w2.x), Al2 = __float_as_uint(w2.y);
        uint32_t Ah3 = __float_as_uint(w3.x), Al3 = __float_as_uint(w3.y);

#pragma unroll
        for (int n = 0; n < 4; ++n) {
            if (n < ntN) {
                int p = (nt0 + n) * 8 + g;
                float q0 = sB[a0o + p] * sB[a0t + p];
                float q1 = sB[a1o + p] * sB[a1t + p];
                uint32_t bh0 = f2tf32(q0);
                uint32_t bh1 = f2tf32(q1);
                uint32_t bl0 = f2tf32(q0 - __uint_as_float(bh0));
                uint32_t bl1 = f2tf32(q1 - __uint_as_float(bh1));
                mma_tf32(Cq[n], Ah0, Ah1, Ah2, Ah3, bh0, bh1);
                mma_tf32(Cq[n], Al0, Al1, Al2, Al3, bh0, bh1);
                mma_tf32(Cq[n], Ah0, Ah1, Ah2, Ah3, bl0, bl1);
            }
        }
    }

    // epilogue: bias + relu + hi/lo split + store to channels 64..95
    float blo = __ldg(&b3[olo]), bhi = __ldg(&b3[ohi]);
#pragma unroll
    for (int n = 0; n < 4; ++n) {
        if (n < ntN) {
#pragma unroll
            for (int e = 0; e < 2; ++e) {
                int col = (nt0 + n) * 8 + 2 * c + e;
                if (col < 100) {
                    float v0 = fmaxf(Cq[n][e] + blo, 0.f);
                    float v1 = fmaxf(Cq[n][2 + e] + bhi, 0.f);
                    float h0, l0, h1, l1;
                    split_tf32(v0, h0, l0);
                    split_tf32(v1, h1, l1);
                    int chl = b * 96 + 64 + olo;
                    int chh = b * 96 + 64 + ohi;
                    g_xc[chl * 3200 + t0 * 25 + col] = h0;
                    g_xcl[chl * XLS + XLP + t0 * 25 + col] = l0;
                    g_xc[chh * 3200 + t0 * 25 + col] = h1;
                    g_xcl[chh * XLS + XLP + t0 * 25 + col] = l1;
                }
            }
        }
    }
}

// ---------------------------------------------------------------------------
// K2: temporal conv GEMM (3xTF32 mma.sync), B-operand pre-split hi/lo.
// hi tile in smem; lo read via LDG (L1-resident). No cvt in hot loop.
// ---------------------------------------------------------------------------
__global__ void __launch_bounds__(256) k2_tconv_mma(const float* __restrict__ bt) {
    extern __shared__ float sxc[];  // hi tile [96][250]: t0-1..t0+8 x 25 j
    int tid = threadIdx.x;
    int b = blockIdx.x >> 4;
    int t0 = (blockIdx.x & 15) * 8;

    for (int idx = tid; idx < 24000; idx += 256) {
        int i = idx / 250, q = idx % 250;
        int gq = (t0 - 1) * 25 + q;
        sxc[idx] = (gq >= 0 && gq < 3200) ? g_xc[(b * 96 + i) * 3200 + gq] : 0.f;
    }
    __syncthreads();

    int warp = tid >> 5, lane = tid & 31;
    int g = lane >> 2, c = lane & 3;
    int mt = warp & 3;
    int half = warp >> 2;
    int nt0 = half ? 13 : 0;
    int ntN = half ? 12 : 13;
    int o0 = mt * 16;
    int o_lo = o0 + g, o_hi = o0 + g + 8;

    float Cacc[13][4];
#pragma unroll
    for (int n = 0; n < 13; ++n) {
        Cacc[n][0] = 0.f; Cacc[n][1] = 0.f;
        Cacc[n][2] = 0.f; Cacc[n][3] = 0.f;
    }

    int posbase = nt0 * 8 + g;

#pragma unroll 1
    for (int kt = 0; kt < 36; ++kt) {
        int k0i = kt * 8 + c;
        int k1i = k0i + 4;
        int i0 = k0i / 3, dt0 = k0i - i0 * 3;
        int i1 = k1i / 3, dt1 = k1i - i1 * 3;
        int ba0 = i0 * 250 + dt0 * 25;
        int ba1 = i1 * 250 + dt1 * 25;
        const float* lp0 = &g_xcl[(b * 96 + i0) * XLS + 3 + (t0 + dt0) * 25];
        const float* lp1 = &g_xcl[(b * 96 + i1) * XLS + 3 + (t0 + dt1) * 25];

        float2 w0 = __ldg(&g_WA2[o_lo * 288 + k0i]);
        float2 w1 = __ldg(&g_WA2[o_hi * 288 + k0i]);
        float2 w2 = __ldg(&g_WA2[o_lo * 288 + k1i]);
        float2 w3 = __ldg(&g_WA2[o_hi * 288 + k1i]);
        uint32_t Ah0 = __float_as_uint(w0.x), Al0 = __float_as_uint(w0.y);
        uint32_t Ah1 = __float_as_uint(w1.x), Al1 = __float_as_uint(w1.y);
        uint32_t Ah2 = __float_as_uint(w2.x), Al2 = __float_as_uint(w2.y);
        uint32_t Ah3 = __float_as_uint(w3.x), Al3 = __float_as_uint(w3.y);

#pragma unroll
        for (int n = 0; n < 13; ++n) {
            if (n < ntN) {
                int posb = posbase + n * 8;
                uint32_t bh0 = __float_as_uint(sxc[ba0 + posb]);
                uint32_t bh1 = __float_as_uint(sxc[ba1 + posb]);
                uint32_t bl0 = __float_as_uint(__ldg(lp0 + posb));
                uint32_t bl1 = __float_as_uint(__ldg(lp1 + posb));
                mma_tf32(Cacc[n], Ah0, Ah1, Ah2, Ah3, bh0, bh1);
                mma_tf32(Cacc[n], Al0, Al1, Al2, Al3, bh0, bh1);
                mma_tf32(Cacc[n], Ah0, Ah1, Ah2, Ah3, bl0, bl1);
            }
        }
    }

    float blo = __ldg(&bt[o_lo]), bhi = __ldg(&bt[o_hi]);
    float sl = 0.f, sl2 = 0.f, sh = 0.f, sh2 = 0.f;
    float* ylo = &g_y[(b * 64 + o_lo) * 3200 + t0 * 25];
    float* yhi = &g_y[(b * 64 + o_hi) * 3200 + t0 * 25];
#pragma unroll
    for (int n = 0; n < 13; ++n) {
        if (n < ntN) {
            int col = (nt0 + n) * 8 + 2 * c;
            float y0 = fmaxf(Cacc[n][0] + blo, 0.f);
            float y1 = fmaxf(Cacc[n][1] + blo, 0.f);
            float y2 = fmaxf(Cacc[n][2] + bhi, 0.f);
            float y3 = fmaxf(Cacc[n][3] + bhi, 0.f);
            *reinterpret_cast<float2*>(ylo + col) = make_float2(y0, y1);
            *reinterpret_cast<float2*>(yhi + col) = make_float2(y2, y3);
            sl += y0 + y1; sl2 += y0 * y0 + y1 * y1;
            sh += y2 + y3; sh2 += y2 * y2 + y3 * y3;
        }
    }
#pragma unroll
    for (int off = 1; off < 4; off <<= 1) {
        sl  += __shfl_xor_sync(0xffffffffu, sl,  off);
        sl2 += __shfl_xor_sync(0xffffffffu, sl2, off);
        sh  += __shfl_xor_sync(0xffffffffu, sh,  off);
        sh2 += __shfl_xor_sync(0xffffffffu, sh2, off);
    }
    __syncthreads();
    if (c == 0) {
        sxc[half * 64 + o_lo] = sl;
        sxc[half * 64 + o_hi] = sh;
        sxc[128 + half * 64 + o_lo] = sl2;
        sxc[128 + half * 64 + o_hi] = sh2;
    }
    __syncthreads();
    if (tid < 64) {
        g_part[tid * 256 + blockIdx.x] = sxc[tid] + sxc[64 + tid];
        g_part[(64 + tid) * 256 + blockIdx.x] = sxc[128 + tid] + sxc[192 + tid];
    }
}

// ---------------------------------------------------------------------------
// K3: BN stats -> scale/shift. grid = 64 (one per channel), 32 threads
// ---------------------------------------------------------------------------
__global__ void k3_stats(const float* __restrict__ gamma,
                         const float* __restrict__ beta) {
    int o = blockIdx.x, lane = threadIdx.x;
    const float4* ps = reinterpret_cast<const float4*>(&g_part[o * 256]);
    const float4* pq = reinterpret_cast<const float4*>(&g_part[(64 + o) * 256]);
    float4 a0 = ps[lane], a1 = ps[lane + 32];
    float4 b0 = pq[lane], b1 = pq[lane + 32];
    float s = (a0.x + a0.y) + (a0.z + a0.w) + (a1.x + a1.y) + (a1.z + a1.w);
    float q = (b0.x + b0.y) + (b0.z + b0.w) + (b1.x + b1.y) + (b1.z + b1.w);
#pragma unroll
    for (int off = 16; off > 0; off >>= 1) {
        s += __shfl_xor_sync(0xffffffffu, s, off);
        q += __shfl_xor_sync(0xffffffffu, q, off);
    }
    if (lane == 0) {
        const float N = (float)(NB * NT * NJ);
        float mean = s / N;
        float var = q / N - mean * mean;
        float sc = __ldg(&gamma[o]) * rsqrtf(var + EPSBN);
        g_scsh[o] = sc;
        g_scsh[64 + o] = __ldg(&beta[o]) - mean * sc;
    }
}

// ---------------------------------------------------------------------------
// K4: affine normalize to output (float4)
// ---------------------------------------------------------------------------
__global__ void k4_norm(float* __restrict__ out) {
    int idx = blockIdx.x * blockDim.x + threadIdx.x;
    const int total4 = NB * NO * NT * NJ / 4;
    if (idx >= total4) return;
    int ch = (idx / 800) & 63;
    float sc = g_scsh[ch], sh = g_scsh[64 + ch];
    const float4* y4 = reinterpret_cast<const float4*>(g_y);
    float4 v = y4[idx];
    v.x = sc * v.x + sh;
    v.y = sc * v.y + sh;
    v.z = sc * v.z + sh;
    v.w = sc * v.w + sh;
    reinterpret_cast<float4*>(out)[idx] = v;
}

// ---------------------------------------------------------------------------
extern "C" void kernel_launch(void* const* d_in, const int* in_sizes, int n_in,
                              void* d_out, int out_size) {
    const float* x = (const float*)d_in[0];
    const float* A = (const float*)d_in[1];
    const float* W1 = (const float*)d_in[2];
    const float* b1 = (const float*)d_in[3];
    const float* W2 = (const float*)d_in[4];
    const float* b2 = (const float*)d_in[5];
    const float* W3 = (const float*)d_in[6];
    const float* b3 = (const float*)d_in[7];
    const float* Wt = (const float*)d_in[8];
    const float* bt = (const float*)d_in[9];
    const float* gamma = (const float*)d_in[10];
    const float* beta = (const float*)d_in[11];

    const int k2_smem = 24000 * sizeof(float);  // 96 KB dynamic
    cudaFuncSetAttribute(k2_tconv_mma,
                         cudaFuncAttributeMaxDynamicSharedMemorySize, k2_smem);

    k0_prep<<<64, 256>>>(A, W3, Wt);
    k1_branches<<<512, 256>>>(x, W1, b1, W2, b2, b3);
    k2_tconv_mma<<<256, 256, k2_smem>>>(bt);
    k3_stats<<<64, 32>>>(gamma, beta);
    k4_norm<<<3200, 256>>>((float*)d_out);
}